// round 9
// baseline (speedup 1.0000x reference)
#include <cuda_runtime.h>
#include <cstdint>

#define T_STEPS 128
#define B_TOT   8192
#define H_DIM   256
#define BETA    0.9f
#define NDIR    16
#define SLACK   1.0205f   // sec(pi/16)=1.01959 + fp margin; strictly conservative

typedef unsigned long long u64;

// --- static device scratch (no allocation allowed) ---
__device__ int           d_cnt[B_TOT];              // survivors per batch
__device__ unsigned char d_list[B_TOT][H_DIM];      // survivor h per batch
__device__ unsigned int  d_pool[B_TOT * H_DIM];     // pooled (b<<8|h), b-sorted
__device__ int           d_total;                   // total survivors

__device__ const float c_cs[NDIR] = {
     1.0f,  0.92387953f,  0.70710678f,  0.38268343f,
     0.0f, -0.38268343f, -0.70710678f, -0.92387953f,
    -1.0f, -0.92387953f, -0.70710678f, -0.38268343f,
     0.0f,  0.38268343f,  0.70710678f,  0.92387953f };
__device__ const float c_sn[NDIR] = {
     0.0f,  0.38268343f,  0.70710678f,  0.92387953f,
     1.0f,  0.92387953f,  0.70710678f,  0.38268343f,
     0.0f, -0.38268343f, -0.70710678f, -0.92387953f,
    -1.0f, -0.92387953f, -0.70710678f, -0.38268343f };

// ---- packed f32x2 helpers ----
__device__ __forceinline__ u64 pk2(float lo, float hi) {
    u64 r; asm("mov.b64 %0, {%1, %2};" : "=l"(r) : "f"(lo), "f"(hi)); return r;
}
__device__ __forceinline__ void unpk2(u64 v, float& lo, float& hi) {
    asm("mov.b64 {%0, %1}, %2;" : "=f"(lo), "=f"(hi) : "l"(v));
}
__device__ __forceinline__ u64 fma2(u64 a, u64 b, u64 c) {
    u64 d; asm("fma.rn.f32x2 %0, %1, %2, %3;" : "=l"(d) : "l"(a), "l"(b), "l"(c)); return d;
}
__device__ __forceinline__ u64 mul2(u64 a, u64 b) {
    u64 d; asm("mul.rn.f32x2 %0, %1, %2;" : "=l"(d) : "l"(a), "l"(b)); return d;
}
__device__ __forceinline__ u64 add2(u64 a, u64 b) {
    u64 d; asm("add.rn.f32x2 %0, %1, %2;" : "=l"(d) : "l"(a), "l"(b)); return d;
}
__device__ __forceinline__ u64 gt1_2(u64 m) {
    u64 r;
    asm("{\n\t"
        ".reg .f32 plo, phi, rl, rh;\n\t"
        "mov.b64 {plo, phi}, %1;\n\t"
        "set.gt.f32.f32 rl, plo, 0f3F800000;\n\t"
        "set.gt.f32.f32 rh, phi, 0f3F800000;\n\t"
        "mov.b64 %0, {rl, rh};\n\t"
        "}" : "=l"(r) : "l"(m));
    return r;
}

// K12: fused directional-max + never-spikes filter + compaction, 16 b per block.
__global__ void __launch_bounds__(256) k12_filter(const float2* __restrict__ x2,
                                                  const float2* __restrict__ w1p,
                                                  float* __restrict__ out) {
    __shared__ float2 sx[T_STEPS][16];   // 16KB
    __shared__ float  sD[16][NDIR];
    __shared__ float  sThr[H_DIM];
    __shared__ int    sSec[H_DIM];

    const int tid = threadIdx.x;
    const int b0  = blockIdx.x * 16;

    {   // per-h precompute
        float2 w = w1p[tid];
        float R  = sqrtf(fmaf(w.x, w.x, w.y * w.y));
        float th = atan2f(w.y, w.x);
        sSec[tid] = ((int)floorf(th * 2.5464790894703255f) + 32) & 15;  // 8/pi
        sThr[tid] = R * SLACK;
    }
    if (tid < 32) out[b0 * 2 + tid] = 0.f;      // zero outputs for this tile

    #pragma unroll
    for (int i = 0; i < 8; ++i) {               // stage x, coalesced
        int idx = tid + i * 256;
        int t = idx >> 4, bl = idx & 15;
        sx[t][bl] = x2[(size_t)t * B_TOT + b0 + bl];
    }
    __syncthreads();

    {   // directional recurrence: thread = (bl, k)
        const int bl = tid >> 4, k = tid & 15;
        const float cs = c_cs[k], sn = c_sn[k];
        float A = 0.f, B = 0.f, D = 0.f;
        #pragma unroll 8
        for (int t = 0; t < T_STEPS; ++t) {
            float2 xv = sx[t][bl];
            A = fmaf(A, BETA, xv.x);
            B = fmaf(B, BETA, xv.y);
            D = fmaxf(D, fmaf(A, cs, B * sn));
        }
        sD[bl][k] = D;
    }
    __syncthreads();

    // filter + per-b compaction: warp w handles bl = 2w, 2w+1
    const int wrp = tid >> 5, lane = tid & 31;
    #pragma unroll
    for (int r = 0; r < 2; ++r) {
        const int bl = wrp * 2 + r;
        const int b  = b0 + bl;
        int cnt = 0;
        #pragma unroll
        for (int c = 0; c < 8; ++c) {
            const int h = c * 32 + lane;
            const int s = sSec[h];
            float mD = fmaxf(sD[bl][s],
                             fmaxf(sD[bl][(s + 1) & 15], sD[bl][(s + 15) & 15]));
            bool pred = (sThr[h] * mD >= 1.0f);
            unsigned mask = __ballot_sync(0xffffffffu, pred);
            if (pred) {
                int pos = cnt + __popc(mask & ((1u << lane) - 1u));
                d_list[b][pos] = (unsigned char)h;
            }
            cnt += __popc(mask);
        }
        if (lane == 0) d_cnt[b] = cnt;
    }
}

// K_pool: single-block prefix scan over d_cnt + deterministic scatter into d_pool.
__global__ void __launch_bounds__(1024) k_pool() {
    __shared__ int wsum[32];
    const int tid = threadIdx.x, lane = tid & 31, wrp = tid >> 5;

    int cnts[8], s = 0;
    #pragma unroll
    for (int i = 0; i < 8; ++i) { cnts[i] = d_cnt[tid * 8 + i]; s += cnts[i]; }

    // inclusive scan of s across 1024 threads
    int v = s;
    #pragma unroll
    for (int off = 1; off < 32; off <<= 1) {
        int n = __shfl_up_sync(0xffffffffu, v, off);
        if (lane >= off) v += n;
    }
    if (lane == 31) wsum[wrp] = v;
    __syncthreads();
    if (wrp == 0) {
        int x = wsum[lane];
        #pragma unroll
        for (int off = 1; off < 32; off <<= 1) {
            int n = __shfl_up_sync(0xffffffffu, x, off);
            if (lane >= off) x += n;
        }
        wsum[lane] = x;
    }
    __syncthreads();

    int base = (wrp ? wsum[wrp - 1] : 0) + v - s;   // exclusive prefix
    #pragma unroll
    for (int i = 0; i < 8; ++i) {
        const int b = tid * 8 + i;
        const int n = cnts[i];
        for (int j = 0; j < n; ++j)
            d_pool[base + j] = ((unsigned)b << 8) | d_list[b][j];
        base += n;
    }
    if (tid == 1023) d_total = wsum[31];
}

// K3: pooled survivor scan. Each warp-pass covers 64 pooled survivors
// (2 packed per lane, possibly different b per half). x per-lane LDG (L2-hot,
// near-contiguous since pool is b-sorted). atomicAdd epilogue.
__global__ void __launch_bounds__(256) k3_scan(const float2* __restrict__ x2,
                                               const float2* __restrict__ w1p,
                                               const float*  __restrict__ w2,
                                               float* __restrict__ out) {
    const int wrp = threadIdx.x >> 5, lane = threadIdx.x & 31;
    const int gwarp  = blockIdx.x * 8 + wrp;
    const int nwarps = gridDim.x * 8;
    const int S = d_total;

    const u64 BETA2 = 0x3F6666663F666666ULL;
    const u64 NEG12 = 0xBF800000BF800000ULL;

    for (int s0 = gwarp * 64; s0 < S; s0 += nwarps * 64) {
        const int ia = s0 + lane, ib = s0 + 32 + lane;
        const bool acta = ia < S, actb = ib < S;
        const unsigned ea = d_pool[acta ? ia : 0];
        const unsigned eb = d_pool[actb ? ib : 0];
        const int ba = ea >> 8, ha = ea & 255;
        const int bb = eb >> 8, hb = eb & 255;

        const float2 wa = w1p[ha], wb = w1p[hb];
        const u64 w0p = pk2(wa.x, wb.x);
        const u64 w1q = pk2(wa.y, wb.y);
        const float2* __restrict__ pa = x2 + ba;
        const float2* __restrict__ pb = x2 + bb;

        u64 m = 0, cnt = 0;
        #pragma unroll 4
        for (int t = 0; t < 118; ++t) {
            float2 xa = __ldg(pa + (size_t)t * B_TOT);
            float2 xb = __ldg(pb + (size_t)t * B_TOT);
            u64 qx = pk2(xa.x, xb.x);
            u64 qy = pk2(xa.y, xb.y);
            u64 s = gt1_2(m);                      // reset from prev mem
            m = fma2(m, BETA2, fma2(qx, w0p, mul2(qy, w1q)));
            m = fma2(s, NEG12, m);
        }
        #pragma unroll
        for (int t = 118; t < T_STEPS; ++t) {
            float2 xa = __ldg(pa + (size_t)t * B_TOT);
            float2 xb = __ldg(pb + (size_t)t * B_TOT);
            u64 qx = pk2(xa.x, xb.x);
            u64 qy = pk2(xa.y, xb.y);
            u64 s = gt1_2(m);
            m = fma2(m, BETA2, fma2(qx, w0p, mul2(qy, w1q)));
            m = fma2(s, NEG12, m);
            cnt = add2(cnt, gt1_2(m));             // spk_t, t in [118,127]
        }

        float ca, cb;
        unpk2(cnt, ca, cb);
        if (acta && ca != 0.f) {
            atomicAdd(&out[ba * 2 + 0], 0.1f * ca * __ldg(&w2[ha]));
            atomicAdd(&out[ba * 2 + 1], 0.1f * ca * __ldg(&w2[H_DIM + ha]));
        }
        if (actb && cb != 0.f) {
            atomicAdd(&out[bb * 2 + 0], 0.1f * cb * __ldg(&w2[hb]));
            atomicAdd(&out[bb * 2 + 1], 0.1f * cb * __ldg(&w2[H_DIM + hb]));
        }
    }
}

extern "C" void kernel_launch(void* const* d_in, const int* in_sizes, int n_in,
                              void* d_out, int out_size) {
    const float2* x  = (const float2*)d_in[0];   // [128, 8192, 2] f32
    const float2* W1 = (const float2*)d_in[1];   // [256, 2] f32
    const float*  W2 = (const float*)d_in[2];    // [2, 256] f32
    float* out = (float*)d_out;                  // [8192, 2] f32

    k12_filter<<<B_TOT / 16, 256>>>(x, W1, out);
    k_pool    <<<1, 1024>>>();
    k3_scan   <<<296, 256>>>(x, W1, W2, out);   // 2368 warps, grid-stride
}

// round 10
// speedup vs baseline: 10.0348x; 10.0348x over previous
#include <cuda_runtime.h>
#include <cstdint>

#define T_STEPS 128
#define B_TOT   8192
#define H_DIM   256
#define BETA    0.9f
#define NDIR    16
#define SLACK   1.0205f   // sec(pi/16)=1.01959 + fp margin; strictly conservative
#define TILE_B  16

typedef unsigned long long u64;

__device__ const float c_cs[NDIR] = {
     1.0f,  0.92387953f,  0.70710678f,  0.38268343f,
     0.0f, -0.38268343f, -0.70710678f, -0.92387953f,
    -1.0f, -0.92387953f, -0.70710678f, -0.38268343f,
     0.0f,  0.38268343f,  0.70710678f,  0.92387953f };
__device__ const float c_sn[NDIR] = {
     0.0f,  0.38268343f,  0.70710678f,  0.92387953f,
     1.0f,  0.92387953f,  0.70710678f,  0.38268343f,
     0.0f, -0.38268343f, -0.70710678f, -0.92387953f,
    -1.0f, -0.92387953f, -0.70710678f, -0.38268343f };

// ---- packed f32x2 helpers ----
__device__ __forceinline__ u64 pk2(float lo, float hi) {
    u64 r; asm("mov.b64 %0, {%1, %2};" : "=l"(r) : "f"(lo), "f"(hi)); return r;
}
__device__ __forceinline__ void unpk2(u64 v, float& lo, float& hi) {
    asm("mov.b64 {%0, %1}, %2;" : "=f"(lo), "=f"(hi) : "l"(v));
}
__device__ __forceinline__ u64 fma2(u64 a, u64 b, u64 c) {
    u64 d; asm("fma.rn.f32x2 %0, %1, %2, %3;" : "=l"(d) : "l"(a), "l"(b), "l"(c)); return d;
}
__device__ __forceinline__ u64 mul2(u64 a, u64 b) {
    u64 d; asm("mul.rn.f32x2 %0, %1, %2;" : "=l"(d) : "l"(a), "l"(b)); return d;
}
__device__ __forceinline__ u64 add2(u64 a, u64 b) {
    u64 d; asm("add.rn.f32x2 %0, %1, %2;" : "=l"(d) : "l"(a), "l"(b)); return d;
}
__device__ __forceinline__ u64 gt1_2(u64 m) {
    u64 r;
    asm("{\n\t"
        ".reg .f32 plo, phi, rl, rh;\n\t"
        "mov.b64 {plo, phi}, %1;\n\t"
        "set.gt.f32.f32 rl, plo, 0f3F800000;\n\t"
        "set.gt.f32.f32 rh, phi, 0f3F800000;\n\t"
        "mov.b64 %0, {rl, rh};\n\t"
        "}" : "=l"(r) : "l"(m));
    return r;
}

// ONE kernel: stage x -> directional bound -> filter+compact (block-local pool)
// -> pooled exact LIF scan from shared -> per-b output (exclusive writer).
__global__ void __launch_bounds__(256)
snn_mega(const float2* __restrict__ x2,   // [T, B] pairs (x0, x1)
         const float2* __restrict__ w1p,  // [H] pairs (W1[h][0], W1[h][1])
         const float*  __restrict__ w2,   // [2, 256]
         float* __restrict__ out)         // [B, 2]
{
    __shared__ float2 sx[T_STEPS][TILE_B];        // 16KB; scan reads are conflict-free
    __shared__ unsigned short spool[TILE_B * H_DIM]; // 8KB worst-case pool
    __shared__ float2 sw1[H_DIM];                 // 2KB
    __shared__ float  sw20[H_DIM], sw21[H_DIM];   // 2KB
    __shared__ float  sThr[H_DIM];                // 1KB  R*SLACK
    __shared__ int    sSec[H_DIM];                // 1KB  sector
    __shared__ float  sD[TILE_B][NDIR];           // 1KB
    __shared__ int    sCnt[TILE_B], sOff[TILE_B + 1];
    __shared__ float  sAcc[TILE_B][2];

    const int tid  = threadIdx.x;
    const int lane = tid & 31, wrp = tid >> 5;
    const int b0   = blockIdx.x * TILE_B;

    // ---- pre: per-h constants + zero accumulators ----
    {
        float2 w = w1p[tid];
        sw1[tid]  = w;
        sw20[tid] = w2[tid];
        sw21[tid] = w2[H_DIM + tid];
        float R  = sqrtf(fmaf(w.x, w.x, w.y * w.y));
        float th = atan2f(w.y, w.x);
        sSec[tid] = ((int)floorf(th * 2.5464790894703255f) + 32) & 15;  // 8/pi
        sThr[tid] = R * SLACK;
    }
    if (tid < TILE_B * 2) ((float*)sAcc)[tid] = 0.f;

    // ---- phase A: stage x (coalesced) ----
    #pragma unroll
    for (int i = 0; i < 8; ++i) {
        int idx = tid + i * 256;
        int t = idx >> 4, bl = idx & 15;
        sx[t][bl] = x2[(size_t)t * B_TOT + b0 + bl];
    }
    __syncthreads();

    // ---- phase B: directional support maxima, thread = (bl, k) ----
    {
        const int bl = tid >> 4, k = tid & 15;
        const float cs = c_cs[k], sn = c_sn[k];
        float A = 0.f, B = 0.f, D = 0.f;
        #pragma unroll 8
        for (int t = 0; t < T_STEPS; ++t) {
            float2 xv = sx[t][bl];
            A = fmaf(A, BETA, xv.x);
            B = fmaf(B, BETA, xv.y);
            D = fmaxf(D, fmaf(A, cs, B * sn));
        }
        sD[bl][k] = D;
    }
    __syncthreads();

    // ---- phase C1: per-b survivor counts (warp w -> bl = 2w, 2w+1) ----
    unsigned predbits[2] = {0u, 0u};   // this lane's pred per 32-h chunk
    #pragma unroll
    for (int r = 0; r < 2; ++r) {
        const int bl = wrp * 2 + r;
        int cnt = 0;
        #pragma unroll
        for (int c = 0; c < 8; ++c) {
            const int h = c * 32 + lane;
            const int s = sSec[h];
            float mD = fmaxf(sD[bl][s],
                             fmaxf(sD[bl][(s + 1) & 15], sD[bl][(s + 15) & 15]));
            bool pred = (sThr[h] * mD >= 1.0f);     // may spike -> survivor
            if (pred) predbits[r] |= (1u << c);
            cnt += __popc(__ballot_sync(0xffffffffu, pred));
        }
        if (lane == 0) sCnt[bl] = cnt;
    }
    __syncthreads();
    if (tid == 0) {                                 // tiny 16-wide exclusive scan
        int s = 0;
        #pragma unroll
        for (int i = 0; i < TILE_B; ++i) { sOff[i] = s; s += sCnt[i]; }
        sOff[TILE_B] = s;
    }
    __syncthreads();

    // ---- phase C2: deterministic scatter into block-local pool ----
    #pragma unroll
    for (int r = 0; r < 2; ++r) {
        const int bl = wrp * 2 + r;
        int base = sOff[bl];
        #pragma unroll
        for (int c = 0; c < 8; ++c) {
            bool pred = (predbits[r] >> c) & 1u;
            unsigned mask = __ballot_sync(0xffffffffu, pred);
            if (pred) {
                int pos = base + __popc(mask & ((1u << lane) - 1u));
                spool[pos] = (unsigned short)((bl << 8) | (c * 32 + lane));
            }
            base += __popc(mask);
        }
    }
    __syncthreads();

    // ---- phase D: pooled exact LIF scan (64 entries per warp-pass) ----
    const int M = sOff[TILE_B];
    const u64 BETA2 = 0x3F6666663F666666ULL;
    const u64 NEG12 = 0xBF800000BF800000ULL;

    for (int s0 = wrp * 64; s0 < M; s0 += 8 * 64) {
        const int ia = s0 + lane, ib = s0 + 32 + lane;
        const bool acta = ia < M, actb = ib < M;
        const unsigned ea = spool[acta ? ia : 0];
        const unsigned eb = spool[actb ? ib : 0];
        const int bla = ea >> 8, ha = ea & 255;
        const int blb = eb >> 8, hb = eb & 255;
        const float2 wa = sw1[ha], wb = sw1[hb];
        const u64 w0p = pk2(wa.x, wb.x);
        const u64 w1q = pk2(wa.y, wb.y);

        u64 m = 0, cnt = 0;
        #pragma unroll 4
        for (int t = 0; t < 118; ++t) {
            float2 xa = sx[t][bla];                 // 16 distinct 8B addrs -> conflict-free
            float2 xb = sx[t][blb];
            u64 qx = pk2(xa.x, xb.x);
            u64 qy = pk2(xa.y, xb.y);
            u64 s = gt1_2(m);                       // reset from prev mem
            m = fma2(m, BETA2, fma2(qx, w0p, mul2(qy, w1q)));
            m = fma2(s, NEG12, m);
        }
        #pragma unroll
        for (int t = 118; t < T_STEPS; ++t) {
            float2 xa = sx[t][bla];
            float2 xb = sx[t][blb];
            u64 qx = pk2(xa.x, xb.x);
            u64 qy = pk2(xa.y, xb.y);
            u64 s = gt1_2(m);
            m = fma2(m, BETA2, fma2(qx, w0p, mul2(qy, w1q)));
            m = fma2(s, NEG12, m);
            cnt = add2(cnt, gt1_2(m));              // spk_t, t in [118,127]
        }

        float ca, cb;
        unpk2(cnt, ca, cb);
        if (acta && ca != 0.f) {
            atomicAdd(&sAcc[bla][0], ca * sw20[ha]);
            atomicAdd(&sAcc[bla][1], ca * sw21[ha]);
        }
        if (actb && cb != 0.f) {
            atomicAdd(&sAcc[blb][0], cb * sw20[hb]);
            atomicAdd(&sAcc[blb][1], cb * sw21[hb]);
        }
    }
    __syncthreads();

    // ---- output: exclusive plain stores (only this block owns these b) ----
    if (tid < TILE_B * 2) {
        int bl = tid >> 1, o = tid & 1;
        out[(b0 + bl) * 2 + o] = 0.1f * sAcc[bl][o];
    }
}

extern "C" void kernel_launch(void* const* d_in, const int* in_sizes, int n_in,
                              void* d_out, int out_size) {
    const float2* x  = (const float2*)d_in[0];   // [128, 8192, 2] f32
    const float2* W1 = (const float2*)d_in[1];   // [256, 2] f32
    const float*  W2 = (const float*)d_in[2];    // [2, 256] f32
    float* out = (float*)d_out;                  // [8192, 2] f32

    snn_mega<<<B_TOT / TILE_B, 256>>>(x, W1, W2, out);
}

// round 11
// speedup vs baseline: 13.4533x; 1.3407x over previous
#include <cuda_runtime.h>
#include <cstdint>

#define T_STEPS 128
#define B_TOT   8192
#define H_DIM   256
#define BETA    0.9f
#define NDIR    32
#define SLACK   1.0060f   // sec(pi/32)=1.00483 + fp margin; strictly conservative
#define TILE_B  8
#define WIN0    118       // first counted step

typedef unsigned long long u64;

__device__ const float c_cs[NDIR] = {
     1.0f,         0.98078528f,  0.92387953f,  0.83146961f,
     0.70710678f,  0.55557023f,  0.38268343f,  0.19509032f,
     0.0f,        -0.19509032f, -0.38268343f, -0.55557023f,
    -0.70710678f, -0.83146961f, -0.92387953f, -0.98078528f,
    -1.0f,        -0.98078528f, -0.92387953f, -0.83146961f,
    -0.70710678f, -0.55557023f, -0.38268343f, -0.19509032f,
     0.0f,         0.19509032f,  0.38268343f,  0.55557023f,
     0.70710678f,  0.83146961f,  0.92387953f,  0.98078528f };
__device__ const float c_sn[NDIR] = {
     0.0f,         0.19509032f,  0.38268343f,  0.55557023f,
     0.70710678f,  0.83146961f,  0.92387953f,  0.98078528f,
     1.0f,         0.98078528f,  0.92387953f,  0.83146961f,
     0.70710678f,  0.55557023f,  0.38268343f,  0.19509032f,
     0.0f,        -0.19509032f, -0.38268343f, -0.55557023f,
    -0.70710678f, -0.83146961f, -0.92387953f, -0.98078528f,
    -1.0f,        -0.98078528f, -0.92387953f, -0.83146961f,
    -0.70710678f, -0.55557023f, -0.38268343f, -0.19509032f };

// ---- packed f32x2 helpers ----
__device__ __forceinline__ u64 pk2(float lo, float hi) {
    u64 r; asm("mov.b64 %0, {%1, %2};" : "=l"(r) : "f"(lo), "f"(hi)); return r;
}
__device__ __forceinline__ void unpk2(u64 v, float& lo, float& hi) {
    asm("mov.b64 {%0, %1}, %2;" : "=f"(lo), "=f"(hi) : "l"(v));
}
__device__ __forceinline__ u64 fma2(u64 a, u64 b, u64 c) {
    u64 d; asm("fma.rn.f32x2 %0, %1, %2, %3;" : "=l"(d) : "l"(a), "l"(b), "l"(c)); return d;
}
__device__ __forceinline__ u64 mul2(u64 a, u64 b) {
    u64 d; asm("mul.rn.f32x2 %0, %1, %2;" : "=l"(d) : "l"(a), "l"(b)); return d;
}
__device__ __forceinline__ u64 add2(u64 a, u64 b) {
    u64 d; asm("add.rn.f32x2 %0, %1, %2;" : "=l"(d) : "l"(a), "l"(b)); return d;
}
__device__ __forceinline__ u64 gt1_2(u64 m) {
    u64 r;
    asm("{\n\t"
        ".reg .f32 plo, phi, rl, rh;\n\t"
        "mov.b64 {plo, phi}, %1;\n\t"
        "set.gt.f32.f32 rl, plo, 0f3F800000;\n\t"
        "set.gt.f32.f32 rh, phi, 0f3F800000;\n\t"
        "mov.b64 %0, {rl, rh};\n\t"
        "}" : "=l"(r) : "l"(m));
    return r;
}

// ONE kernel. Filter: mem_t <= L_t = w.v_t (resets only subtract), and only
// spikes at t in [118,127] matter. So if max_{t in window} L_t <= 1 the neuron
// contributes EXACTLY 0. Directional bound on the WINDOW max (32 sectors).
__global__ void __launch_bounds__(256)
snn_mega(const float2* __restrict__ x2,   // [T, B] pairs (x0, x1)
         const float2* __restrict__ w1p,  // [H] pairs (W1[h][0], W1[h][1])
         const float*  __restrict__ w2,   // [2, 256]
         float* __restrict__ out)         // [B, 2]
{
    __shared__ float2 sx[T_STEPS][TILE_B];           // 8KB
    __shared__ unsigned short spool[TILE_B * H_DIM]; // 4KB worst case
    __shared__ float2 sw1[H_DIM];                    // 2KB
    __shared__ float  sw20[H_DIM], sw21[H_DIM];      // 2KB
    __shared__ float  sThr[H_DIM];                   // 1KB  R*SLACK
    __shared__ int    sSec[H_DIM];                   // 1KB  sector
    __shared__ float  sD[TILE_B][NDIR];              // 1KB  window dir-max
    __shared__ int    sCnt[TILE_B], sOff[TILE_B + 1];
    __shared__ float  sAcc[TILE_B][2];

    const int tid  = threadIdx.x;
    const int lane = tid & 31, wrp = tid >> 5;
    const int b0   = blockIdx.x * TILE_B;

    // ---- pre: per-h constants + zero accumulators ----
    {
        float2 w = w1p[tid];
        sw1[tid]  = w;
        sw20[tid] = w2[tid];
        sw21[tid] = w2[H_DIM + tid];
        float R  = sqrtf(fmaf(w.x, w.x, w.y * w.y));
        float th = atan2f(w.y, w.x);
        sSec[tid] = ((int)floorf(th * 5.092958178940651f) + 64) & 31;  // 16/pi
        sThr[tid] = R * SLACK;
    }
    if (tid < TILE_B * 2) ((float*)sAcc)[tid] = 0.f;

    // ---- phase A: stage x (coalesced per t-row) ----
    #pragma unroll
    for (int i = 0; i < 4; ++i) {
        int idx = tid + i * 256;
        int t = idx >> 3, bl = idx & 7;
        sx[t][bl] = x2[(size_t)t * B_TOT + b0 + bl];
    }
    __syncthreads();

    // ---- phase B: v recurrence; dir-max over WINDOW only. thread = (bl, k) ----
    {
        const int bl = tid >> 5, k = tid & 31;      // lane k: sx read is broadcast
        const float cs = c_cs[k], sn = c_sn[k];
        float A = 0.f, B = 0.f;
        #pragma unroll 8
        for (int t = 0; t < WIN0; ++t) {
            float2 xv = sx[t][bl];
            A = fmaf(A, BETA, xv.x);
            B = fmaf(B, BETA, xv.y);
        }
        float D = 0.f;                               // clamp at 0 (R*0 < 1)
        #pragma unroll
        for (int t = WIN0; t < T_STEPS; ++t) {
            float2 xv = sx[t][bl];
            A = fmaf(A, BETA, xv.x);
            B = fmaf(B, BETA, xv.y);
            D = fmaxf(D, fmaf(A, cs, B * sn));
        }
        sD[bl][k] = D;
    }
    __syncthreads();

    // ---- phase C1: survivor counts (warp w -> bl = w) ----
    unsigned predbits = 0u;
    {
        const int bl = wrp;
        int cnt = 0;
        #pragma unroll
        for (int c = 0; c < 8; ++c) {
            const int h = c * 32 + lane;
            const int s = sSec[h];
            float mD = fmaxf(sD[bl][s],
                             fmaxf(sD[bl][(s + 1) & 31], sD[bl][(s + 31) & 31]));
            bool pred = (sThr[h] * mD >= 1.0f);     // may spike in window
            if (pred) predbits |= (1u << c);
            cnt += __popc(__ballot_sync(0xffffffffu, pred));
        }
        if (lane == 0) sCnt[bl] = cnt;
    }
    __syncthreads();
    if (tid == 0) {
        int s = 0;
        #pragma unroll
        for (int i = 0; i < TILE_B; ++i) { sOff[i] = s; s += sCnt[i]; }
        sOff[TILE_B] = s;
    }
    __syncthreads();

    // ---- phase C2: deterministic scatter into block-local pool ----
    {
        const int bl = wrp;
        int base = sOff[bl];
        #pragma unroll
        for (int c = 0; c < 8; ++c) {
            bool pred = (predbits >> c) & 1u;
            unsigned mask = __ballot_sync(0xffffffffu, pred);
            if (pred) {
                int pos = base + __popc(mask & ((1u << lane) - 1u));
                spool[pos] = (unsigned short)((bl << 8) | (c * 32 + lane));
            }
            base += __popc(mask);
        }
    }
    __syncthreads();

    // ---- phase D: pooled exact LIF scan (64 entries per warp-pass) ----
    const int M = sOff[TILE_B];
    const u64 BETA2 = 0x3F6666663F666666ULL;
    const u64 NEG12 = 0xBF800000BF800000ULL;

    for (int s0 = wrp * 64; s0 < M; s0 += 8 * 64) {
        const int ia = s0 + lane, ib = s0 + 32 + lane;
        const bool acta = ia < M, actb = ib < M;
        const unsigned ea = spool[acta ? ia : 0];
        const unsigned eb = spool[actb ? ib : 0];
        const int bla = ea >> 8, ha = ea & 255;
        const int blb = eb >> 8, hb = eb & 255;
        const float2 wa = sw1[ha], wb = sw1[hb];
        const u64 w0p = pk2(wa.x, wb.x);
        const u64 w1q = pk2(wa.y, wb.y);

        u64 m = 0, cnt = 0;
        #pragma unroll 4
        for (int t = 0; t < WIN0; ++t) {
            float2 xa = sx[t][bla];                 // <=8 distinct addrs: conflict-free
            float2 xb = sx[t][blb];
            u64 qx = pk2(xa.x, xb.x);
            u64 qy = pk2(xa.y, xb.y);
            u64 s = gt1_2(m);                       // reset from prev mem
            m = fma2(m, BETA2, fma2(qx, w0p, mul2(qy, w1q)));
            m = fma2(s, NEG12, m);
        }
        #pragma unroll
        for (int t = WIN0; t < T_STEPS; ++t) {
            float2 xa = sx[t][bla];
            float2 xb = sx[t][blb];
            u64 qx = pk2(xa.x, xb.x);
            u64 qy = pk2(xa.y, xb.y);
            u64 s = gt1_2(m);
            m = fma2(m, BETA2, fma2(qx, w0p, mul2(qy, w1q)));
            m = fma2(s, NEG12, m);
            cnt = add2(cnt, gt1_2(m));              // spk_t, t in [118,127]
        }

        float ca, cb;
        unpk2(cnt, ca, cb);
        if (acta && ca != 0.f) {
            atomicAdd(&sAcc[bla][0], ca * sw20[ha]);
            atomicAdd(&sAcc[bla][1], ca * sw21[ha]);
        }
        if (actb && cb != 0.f) {
            atomicAdd(&sAcc[blb][0], cb * sw20[hb]);
            atomicAdd(&sAcc[blb][1], cb * sw21[hb]);
        }
    }
    __syncthreads();

    // ---- output: exclusive plain stores ----
    if (tid < TILE_B * 2) {
        int bl = tid >> 1, o = tid & 1;
        out[(b0 + bl) * 2 + o] = 0.1f * sAcc[bl][o];
    }
}

extern "C" void kernel_launch(void* const* d_in, const int* in_sizes, int n_in,
                              void* d_out, int out_size) {
    const float2* x  = (const float2*)d_in[0];   // [128, 8192, 2] f32
    const float2* W1 = (const float2*)d_in[1];   // [256, 2] f32
    const float*  W2 = (const float*)d_in[2];    // [2, 256] f32
    float* out = (float*)d_out;                  // [8192, 2] f32

    snn_mega<<<B_TOT / TILE_B, 256>>>(x, W1, W2, out);
}

// round 12
// speedup vs baseline: 14.7500x; 1.0964x over previous
#include <cuda_runtime.h>
#include <cstdint>

#define T_STEPS 128
#define B_TOT   8192
#define H_DIM   256
#define BETA    0.9f
#define NDIR    32
#define SLACK   1.0060f   // sec(pi/32)=1.00483 + fp margin; strictly conservative
#define TILE_B  16
#define WIN0    118       // first counted step

typedef unsigned long long u64;

// --- static device scratch (no allocation allowed) ---
__device__ float4 g_hinfo[H_DIM];   // {w0, w1, R*SLACK, sector(as int bits)}
__device__ float2 g_w2[H_DIM];      // {W2[0][h], W2[1][h]}

__device__ const float c_cs[NDIR] = {
     1.0f,         0.98078528f,  0.92387953f,  0.83146961f,
     0.70710678f,  0.55557023f,  0.38268343f,  0.19509032f,
     0.0f,        -0.19509032f, -0.38268343f, -0.55557023f,
    -0.70710678f, -0.83146961f, -0.92387953f, -0.98078528f,
    -1.0f,        -0.98078528f, -0.92387953f, -0.83146961f,
    -0.70710678f, -0.55557023f, -0.38268343f, -0.19509032f,
     0.0f,         0.19509032f,  0.38268343f,  0.55557023f,
     0.70710678f,  0.83146961f,  0.92387953f,  0.98078528f };
__device__ const float c_sn[NDIR] = {
     0.0f,         0.19509032f,  0.38268343f,  0.55557023f,
     0.70710678f,  0.83146961f,  0.92387953f,  0.98078528f,
     1.0f,         0.98078528f,  0.92387953f,  0.83146961f,
     0.70710678f,  0.55557023f,  0.38268343f,  0.19509032f,
     0.0f,        -0.19509032f, -0.38268343f, -0.55557023f,
    -0.70710678f, -0.83146961f, -0.92387953f, -0.98078528f,
    -1.0f,        -0.98078528f, -0.92387953f, -0.83146961f,
    -0.70710678f, -0.55557023f, -0.38268343f, -0.19509032f };

// ---- packed f32x2 helpers ----
__device__ __forceinline__ u64 pk2(float lo, float hi) {
    u64 r; asm("mov.b64 %0, {%1, %2};" : "=l"(r) : "f"(lo), "f"(hi)); return r;
}
__device__ __forceinline__ void unpk2(u64 v, float& lo, float& hi) {
    asm("mov.b64 {%0, %1}, %2;" : "=f"(lo), "=f"(hi) : "l"(v));
}
__device__ __forceinline__ u64 fma2(u64 a, u64 b, u64 c) {
    u64 d; asm("fma.rn.f32x2 %0, %1, %2, %3;" : "=l"(d) : "l"(a), "l"(b), "l"(c)); return d;
}
__device__ __forceinline__ u64 mul2(u64 a, u64 b) {
    u64 d; asm("mul.rn.f32x2 %0, %1, %2;" : "=l"(d) : "l"(a), "l"(b)); return d;
}
__device__ __forceinline__ u64 add2(u64 a, u64 b) {
    u64 d; asm("add.rn.f32x2 %0, %1, %2;" : "=l"(d) : "l"(a), "l"(b)); return d;
}
__device__ __forceinline__ u64 gt1_2(u64 m) {
    u64 r;
    asm("{\n\t"
        ".reg .f32 plo, phi, rl, rh;\n\t"
        "mov.b64 {plo, phi}, %1;\n\t"
        "set.gt.f32.f32 rl, plo, 0f3F800000;\n\t"
        "set.gt.f32.f32 rh, phi, 0f3F800000;\n\t"
        "mov.b64 %0, {rl, rh};\n\t"
        "}" : "=l"(r) : "l"(m));
    return r;
}

// K_pre: one block, per-h constants computed ONCE (atan2/sqrt hoisted out of
// the 512 main blocks).
__global__ void __launch_bounds__(H_DIM) k_pre(const float2* __restrict__ w1p,
                                               const float*  __restrict__ w2) {
    int h = threadIdx.x;
    float2 w = w1p[h];
    float R  = sqrtf(fmaf(w.x, w.x, w.y * w.y));
    float th = atan2f(w.y, w.x);
    int sec  = ((int)floorf(th * 5.092958178940651f) + 64) & 31;  // 16/pi
    g_hinfo[h] = make_float4(w.x, w.y, R * SLACK, __int_as_float(sec));
    g_w2[h]    = make_float2(w2[h], w2[H_DIM + h]);
}

// Main kernel. Filter: mem_t <= L_t = w.v_t (resets only subtract); only
// spikes at t in [118,127] matter; if window max L <= 1 -> contributes 0.
__global__ void __launch_bounds__(256)
snn_mega(const float2* __restrict__ x2,   // [T, B] pairs (x0, x1)
         float* __restrict__ out)         // [B, 2]
{
    __shared__ float2 sx[T_STEPS][TILE_B];           // 16KB
    __shared__ unsigned short spool[TILE_B * H_DIM]; // 8KB worst case
    __shared__ float2 sw1[H_DIM];                    // 2KB
    __shared__ float  sw20[H_DIM], sw21[H_DIM];      // 2KB
    __shared__ float  sThr[H_DIM];                   // 1KB
    __shared__ int    sSec[H_DIM];                   // 1KB
    __shared__ float  sD[TILE_B][NDIR];              // 2KB
    __shared__ int    sCnt[TILE_B], sOff[TILE_B + 1];
    __shared__ float  sAcc[TILE_B][2];

    const int tid  = threadIdx.x;
    const int lane = tid & 31, wrp = tid >> 5;
    const int b0   = blockIdx.x * TILE_B;

    // ---- pre: load per-h tables (precomputed) ----
    {
        float4 hi = g_hinfo[tid];
        sw1[tid]  = make_float2(hi.x, hi.y);
        sThr[tid] = hi.z;
        sSec[tid] = __float_as_int(hi.w);
        float2 w2v = g_w2[tid];
        sw20[tid] = w2v.x;
        sw21[tid] = w2v.y;
    }
    if (tid < TILE_B * 2) ((float*)sAcc)[tid] = 0.f;

    // ---- phase A: stage x (coalesced per t-row) ----
    #pragma unroll
    for (int i = 0; i < 8; ++i) {
        int idx = tid + i * 256;
        int t = idx >> 4, bl = idx & 15;
        sx[t][bl] = x2[(size_t)t * B_TOT + b0 + bl];
    }
    __syncthreads();

    // ---- phase B: v recurrence, 2 tasks/thread (4 indep FFMA chains) ----
    {
        const int k   = tid & 31;
        const int bl0 = tid >> 5, bl1 = bl0 + 8;
        const float cs = c_cs[k], sn = c_sn[k];
        float A0 = 0.f, B0 = 0.f, A1 = 0.f, B1 = 0.f;
        #pragma unroll 8
        for (int t = 0; t < WIN0; ++t) {
            float2 x0 = sx[t][bl0];
            float2 x1 = sx[t][bl1];
            A0 = fmaf(A0, BETA, x0.x);  B0 = fmaf(B0, BETA, x0.y);
            A1 = fmaf(A1, BETA, x1.x);  B1 = fmaf(B1, BETA, x1.y);
        }
        float D0 = 0.f, D1 = 0.f;                   // clamp at 0
        #pragma unroll
        for (int t = WIN0; t < T_STEPS; ++t) {
            float2 x0 = sx[t][bl0];
            float2 x1 = sx[t][bl1];
            A0 = fmaf(A0, BETA, x0.x);  B0 = fmaf(B0, BETA, x0.y);
            A1 = fmaf(A1, BETA, x1.x);  B1 = fmaf(B1, BETA, x1.y);
            D0 = fmaxf(D0, fmaf(A0, cs, B0 * sn));
            D1 = fmaxf(D1, fmaf(A1, cs, B1 * sn));
        }
        sD[bl0][k] = D0;
        sD[bl1][k] = D1;
    }
    __syncthreads();

    // ---- phase C1: survivor counts (warp w -> bl = w, w+8) ----
    unsigned predbits[2] = {0u, 0u};
    #pragma unroll
    for (int r = 0; r < 2; ++r) {
        const int bl = wrp + r * 8;
        int cnt = 0;
        #pragma unroll
        for (int c = 0; c < 8; ++c) {
            const int h = c * 32 + lane;
            const int s = sSec[h];
            float mD = fmaxf(sD[bl][s],
                             fmaxf(sD[bl][(s + 1) & 31], sD[bl][(s + 31) & 31]));
            bool pred = (sThr[h] * mD >= 1.0f);     // may spike in window
            if (pred) predbits[r] |= (1u << c);
            cnt += __popc(__ballot_sync(0xffffffffu, pred));
        }
        if (lane == 0) sCnt[bl] = cnt;
    }
    __syncthreads();
    if (tid == 0) {
        int s = 0;
        #pragma unroll
        for (int i = 0; i < TILE_B; ++i) { sOff[i] = s; s += sCnt[i]; }
        sOff[TILE_B] = s;
    }
    __syncthreads();

    // ---- phase C2: deterministic scatter into block-local pool ----
    #pragma unroll
    for (int r = 0; r < 2; ++r) {
        const int bl = wrp + r * 8;
        int base = sOff[bl];
        #pragma unroll
        for (int c = 0; c < 8; ++c) {
            bool pred = (predbits[r] >> c) & 1u;
            unsigned mask = __ballot_sync(0xffffffffu, pred);
            if (pred) {
                int pos = base + __popc(mask & ((1u << lane) - 1u));
                spool[pos] = (unsigned short)((bl << 8) | (c * 32 + lane));
            }
            base += __popc(mask);
        }
    }
    __syncthreads();

    // ---- phase D: pooled exact LIF scan (64 entries per warp-pass) ----
    const int M = sOff[TILE_B];
    const u64 BETA2 = 0x3F6666663F666666ULL;
    const u64 NEG12 = 0xBF800000BF800000ULL;

    for (int s0 = wrp * 64; s0 < M; s0 += 8 * 64) {
        const int ia = s0 + lane, ib = s0 + 32 + lane;
        const bool acta = ia < M, actb = ib < M;
        const unsigned ea = spool[acta ? ia : 0];
        const unsigned eb = spool[actb ? ib : 0];
        const int bla = ea >> 8, ha = ea & 255;
        const int blb = eb >> 8, hb = eb & 255;
        const float2 wa = sw1[ha], wb = sw1[hb];
        const u64 w0p = pk2(wa.x, wb.x);
        const u64 w1q = pk2(wa.y, wb.y);

        u64 m = 0, cnt = 0;
        #pragma unroll 4
        for (int t = 0; t < WIN0; ++t) {
            float2 xa = sx[t][bla];
            float2 xb = sx[t][blb];
            u64 qx = pk2(xa.x, xb.x);
            u64 qy = pk2(xa.y, xb.y);
            u64 s = gt1_2(m);                       // reset from prev mem
            m = fma2(m, BETA2, fma2(qx, w0p, mul2(qy, w1q)));
            m = fma2(s, NEG12, m);
        }
        #pragma unroll
        for (int t = WIN0; t < T_STEPS; ++t) {
            float2 xa = sx[t][bla];
            float2 xb = sx[t][blb];
            u64 qx = pk2(xa.x, xb.x);
            u64 qy = pk2(xa.y, xb.y);
            u64 s = gt1_2(m);
            m = fma2(m, BETA2, fma2(qx, w0p, mul2(qy, w1q)));
            m = fma2(s, NEG12, m);
            cnt = add2(cnt, gt1_2(m));              // spk_t, t in [118,127]
        }

        float ca, cb;
        unpk2(cnt, ca, cb);
        if (acta && ca != 0.f) {
            atomicAdd(&sAcc[bla][0], ca * sw20[ha]);
            atomicAdd(&sAcc[bla][1], ca * sw21[ha]);
        }
        if (actb && cb != 0.f) {
            atomicAdd(&sAcc[blb][0], cb * sw20[hb]);
            atomicAdd(&sAcc[blb][1], cb * sw21[hb]);
        }
    }
    __syncthreads();

    // ---- output: exclusive plain stores ----
    if (tid < TILE_B * 2) {
        int bl = tid >> 1, o = tid & 1;
        out[(b0 + bl) * 2 + o] = 0.1f * sAcc[bl][o];
    }
}

extern "C" void kernel_launch(void* const* d_in, const int* in_sizes, int n_in,
                              void* d_out, int out_size) {
    const float2* x  = (const float2*)d_in[0];   // [128, 8192, 2] f32
    const float2* W1 = (const float2*)d_in[1];   // [256, 2] f32
    const float*  W2 = (const float*)d_in[2];    // [2, 256] f32
    float* out = (float*)d_out;                  // [8192, 2] f32

    k_pre   <<<1, H_DIM>>>(W1, W2);
    snn_mega<<<B_TOT / TILE_B, 256>>>(x, out);
}

// round 13
// speedup vs baseline: 16.5439x; 1.1216x over previous
#include <cuda_runtime.h>
#include <cstdint>

#define T_STEPS 128
#define B_TOT   8192
#define H_DIM   256
#define BETA    0.9f
#define NDIR    32
#define TILE_B  16
#define WIN0    118
#define NWIN    (T_STEPS - WIN0)   // 10
#define MARGIN  1.002f

typedef unsigned long long u64;

// --- static device scratch (no allocation allowed) ---
__device__ float4 g_hinfo[H_DIM];   // {w0, w1, a*R*MARGIN, b*R*MARGIN}
__device__ int    g_sec[H_DIM];
__device__ float2 g_w2[H_DIM];      // {W2[0][h], W2[1][h]}

__device__ const float c_cs[NDIR] = {
     1.0f,         0.98078528f,  0.92387953f,  0.83146961f,
     0.70710678f,  0.55557023f,  0.38268343f,  0.19509032f,
     0.0f,        -0.19509032f, -0.38268343f, -0.55557023f,
    -0.70710678f, -0.83146961f, -0.92387953f, -0.98078528f,
    -1.0f,        -0.98078528f, -0.92387953f, -0.83146961f,
    -0.70710678f, -0.55557023f, -0.38268343f, -0.19509032f,
     0.0f,         0.19509032f,  0.38268343f,  0.55557023f,
     0.70710678f,  0.83146961f,  0.92387953f,  0.98078528f };
__device__ const float c_sn[NDIR] = {
     0.0f,         0.19509032f,  0.38268343f,  0.55557023f,
     0.70710678f,  0.83146961f,  0.92387953f,  0.98078528f,
     1.0f,         0.98078528f,  0.92387953f,  0.83146961f,
     0.70710678f,  0.55557023f,  0.38268343f,  0.19509032f,
     0.0f,        -0.19509032f, -0.38268343f, -0.55557023f,
    -0.70710678f, -0.83146961f, -0.92387953f, -0.98078528f,
    -1.0f,        -0.98078528f, -0.92387953f, -0.83146961f,
    -0.70710678f, -0.55557023f, -0.38268343f, -0.19509032f };
// beta^(8m), m = 0..15
__device__ const float c_pow8[16] = {
    1.0f, 0.43046721f, 0.18530202f, 0.079766443f,
    0.034336838f, 0.014780883f, 0.0063626854f, 0.0027389442f,
    0.0011790185f, 0.00050752909f, 0.00021847450f, 9.4046100e-05f,
    4.0483775e-05f, 1.7426963e-05f, 7.5018138e-06f, 3.2295300e-06f };

// ---- packed f32x2 helpers ----
__device__ __forceinline__ u64 pk2(float lo, float hi) {
    u64 r; asm("mov.b64 %0, {%1, %2};" : "=l"(r) : "f"(lo), "f"(hi)); return r;
}
__device__ __forceinline__ void unpk2(u64 v, float& lo, float& hi) {
    asm("mov.b64 {%0, %1}, %2;" : "=f"(lo), "=f"(hi) : "l"(v));
}
__device__ __forceinline__ u64 fma2(u64 a, u64 b, u64 c) {
    u64 d; asm("fma.rn.f32x2 %0, %1, %2, %3;" : "=l"(d) : "l"(a), "l"(b), "l"(c)); return d;
}
__device__ __forceinline__ u64 mul2(u64 a, u64 b) {
    u64 d; asm("mul.rn.f32x2 %0, %1, %2;" : "=l"(d) : "l"(a), "l"(b)); return d;
}
__device__ __forceinline__ u64 add2(u64 a, u64 b) {
    u64 d; asm("add.rn.f32x2 %0, %1, %2;" : "=l"(d) : "l"(a), "l"(b)); return d;
}
__device__ __forceinline__ u64 gt1_2(u64 m) {
    u64 r;
    asm("{\n\t"
        ".reg .f32 plo, phi, rl, rh;\n\t"
        "mov.b64 {plo, phi}, %1;\n\t"
        "set.gt.f32.f32 rl, plo, 0f3F800000;\n\t"
        "set.gt.f32.f32 rh, phi, 0f3F800000;\n\t"
        "mov.b64 %0, {rl, rh};\n\t"
        "}" : "=l"(r) : "l"(m));
    return r;
}

// K_pre: per-h constants once. Sector decomposition w/R = a*u_k + b*u_{k+1},
// a,b >= 0; support subadditivity gives max_t w.v_t <= R(a*D_k + b*D_{k+1}).
__global__ void __launch_bounds__(H_DIM) k_pre(const float2* __restrict__ w1p,
                                               const float*  __restrict__ w2) {
    int h = threadIdx.x;
    float2 w = w1p[h];
    float R  = sqrtf(fmaf(w.x, w.x, w.y * w.y));
    float th = atan2f(w.y, w.x);
    int k  = ((int)floorf(th * 5.092958178940651f) + 64) & 31;   // 16/pi
    int k1 = (k + 1) & 31;
    const float inv_det = 1.0f / 0.19509032201612825f;           // 1/sin(pi/16)
    float iR = 1.0f / fmaxf(R, 1e-30f);
    float nx = w.x * iR, ny = w.y * iR;
    float a = (nx * c_sn[k1] - ny * c_cs[k1]) * inv_det;
    float b = (ny * c_cs[k]  - nx * c_sn[k])  * inv_det;
    a = fmaxf(a, 0.f);  b = fmaxf(b, 0.f);
    g_hinfo[h] = make_float4(w.x, w.y, a * R * MARGIN, b * R * MARGIN);
    g_sec[h]   = k;
    g_w2[h]    = make_float2(w2[h], w2[H_DIM + h]);
}

__global__ void __launch_bounds__(256)
snn_mega(const float2* __restrict__ x2,   // [T, B] pairs (x0, x1)
         float* __restrict__ out)         // [B, 2]
{
    __shared__ float2 sx[T_STEPS][TILE_B];           // 16KB raw x (phase D uses it)
    __shared__ unsigned short spool[TILE_B * H_DIM]; // 8KB worst case
    __shared__ float2 sw1[H_DIM];                    // 2KB
    __shared__ float  sw20[H_DIM], sw21[H_DIM];      // 2KB
    __shared__ float  sCa[H_DIM], sCb[H_DIM];        // 2KB  interp coefs (*R*margin)
    __shared__ int    sSec[H_DIM];                   // 1KB
    __shared__ float  sD[TILE_B][NDIR];              // 2KB  window dir support
    __shared__ float2 sEnd[16][TILE_B];              // 2KB  segment end sums
    __shared__ float2 sVw[NWIN][TILE_B];             // 1.25KB window v values
    __shared__ int    sCnt[TILE_B], sOff[TILE_B + 1];
    __shared__ float  sAcc[TILE_B][2];

    const int tid  = threadIdx.x;
    const int lane = tid & 31, wrp = tid >> 5;
    const int b0   = blockIdx.x * TILE_B;

    // ---- tables ----
    {
        float4 hi = g_hinfo[tid];
        sw1[tid] = make_float2(hi.x, hi.y);
        sCa[tid] = hi.z;
        sCb[tid] = hi.w;
        sSec[tid] = g_sec[tid];
        float2 w2v = g_w2[tid];
        sw20[tid] = w2v.x;
        sw21[tid] = w2v.y;
    }
    if (tid < TILE_B * 2) ((float*)sAcc)[tid] = 0.f;

    // ---- phase A: stage x (coalesced per t-row) ----
    #pragma unroll
    for (int i = 0; i < 8; ++i) {
        int idx = tid + i * 256;
        int t = idx >> 4, bl = idx & 15;
        sx[t][bl] = x2[(size_t)t * B_TOT + b0 + bl];
    }
    __syncthreads();

    // ---- phase B1: segmented scan local sums (thread = (segment j, bl)) ----
    {
        const int j = tid >> 4, bl = tid & 15;
        float A = 0.f, Bv = 0.f;
        #pragma unroll
        for (int i = 0; i < 8; ++i) {
            float2 xv = sx[8 * j + i][bl];
            A  = fmaf(A,  BETA, xv.x);
            Bv = fmaf(Bv, BETA, xv.y);
        }
        sEnd[j][bl] = make_float2(A, Bv);
    }
    __syncthreads();

    // ---- phase B2: window-owning segments reconstruct v_t, t in [118,128) ----
    {
        const int j = tid >> 4, bl = tid & 15;
        if (j >= 14) {
            float VA = 0.f, VB = 0.f;                 // v_{8j-1}
            for (int i = 0; i < j; ++i) {
                float2 e = sEnd[i][bl];
                float p = c_pow8[j - 1 - i];
                VA = fmaf(e.x, p, VA);
                VB = fmaf(e.y, p, VB);
            }
            #pragma unroll
            for (int i = 0; i < 8; ++i) {
                float2 xv = sx[8 * j + i][bl];
                VA = fmaf(VA, BETA, xv.x);
                VB = fmaf(VB, BETA, xv.y);
                int t = 8 * j + i;
                if (t >= WIN0) sVw[t - WIN0][bl] = make_float2(VA, VB);
            }
        }
    }
    __syncthreads();

    // ---- phase B3: directional window support (2 tasks/thread) ----
    {
        const int k = tid & 31;
        const int bl0 = tid >> 5, bl1 = bl0 + 8;
        const float cs = c_cs[k], sn = c_sn[k];
        float D0 = -1e30f, D1 = -1e30f;
        #pragma unroll
        for (int i = 0; i < NWIN; ++i) {
            float2 v0 = sVw[i][bl0];
            float2 v1 = sVw[i][bl1];
            D0 = fmaxf(D0, fmaf(v0.x, cs, v0.y * sn));
            D1 = fmaxf(D1, fmaf(v1.x, cs, v1.y * sn));
        }
        sD[bl0][k] = D0;
        sD[bl1][k] = D1;
    }
    __syncthreads();

    // ---- phase C1: survivor counts (warp w -> bl = w, w+8) ----
    unsigned predbits[2] = {0u, 0u};
    #pragma unroll
    for (int r = 0; r < 2; ++r) {
        const int bl = wrp + r * 8;
        int cnt = 0;
        #pragma unroll
        for (int c = 0; c < 8; ++c) {
            const int h = c * 32 + lane;
            const int k = sSec[h];
            float bound = sCa[h] * sD[bl][k] + sCb[h] * sD[bl][(k + 1) & 31];
            bool pred = (bound >= 0.999f);            // may spike in window
            if (pred) predbits[r] |= (1u << c);
            cnt += __popc(__ballot_sync(0xffffffffu, pred));
        }
        if (lane == 0) sCnt[bl] = cnt;
    }
    __syncthreads();
    if (tid == 0) {
        int s = 0;
        #pragma unroll
        for (int i = 0; i < TILE_B; ++i) { sOff[i] = s; s += sCnt[i]; }
        sOff[TILE_B] = s;
    }
    __syncthreads();

    // ---- phase C2: deterministic scatter into block-local pool ----
    #pragma unroll
    for (int r = 0; r < 2; ++r) {
        const int bl = wrp + r * 8;
        int base = sOff[bl];
        #pragma unroll
        for (int c = 0; c < 8; ++c) {
            bool pred = (predbits[r] >> c) & 1u;
            unsigned mask = __ballot_sync(0xffffffffu, pred);
            if (pred) {
                int pos = base + __popc(mask & ((1u << lane) - 1u));
                spool[pos] = (unsigned short)((bl << 8) | (c * 32 + lane));
            }
            base += __popc(mask);
        }
    }
    __syncthreads();

    // ---- phase D: pooled exact LIF scan on raw x (fp path unchanged) ----
    const int M = sOff[TILE_B];
    const u64 BETA2 = 0x3F6666663F666666ULL;
    const u64 NEG12 = 0xBF800000BF800000ULL;

    for (int s0 = wrp * 64; s0 < M; s0 += 8 * 64) {
        const int ia = s0 + lane, ib = s0 + 32 + lane;
        const bool acta = ia < M, actb = ib < M;
        const unsigned ea = spool[acta ? ia : 0];
        const unsigned eb = spool[actb ? ib : 0];
        const int bla = ea >> 8, ha = ea & 255;
        const int blb = eb >> 8, hb = eb & 255;
        const float2 wa = sw1[ha], wb = sw1[hb];
        const u64 w0p = pk2(wa.x, wb.x);
        const u64 w1q = pk2(wa.y, wb.y);

        u64 m = 0, cnt = 0;
        #pragma unroll 4
        for (int t = 0; t < WIN0; ++t) {
            float2 xa = sx[t][bla];
            float2 xb = sx[t][blb];
            u64 qx = pk2(xa.x, xb.x);
            u64 qy = pk2(xa.y, xb.y);
            u64 s = gt1_2(m);                       // reset from prev mem
            m = fma2(m, BETA2, fma2(qx, w0p, mul2(qy, w1q)));
            m = fma2(s, NEG12, m);
        }
        #pragma unroll
        for (int t = WIN0; t < T_STEPS; ++t) {
            float2 xa = sx[t][bla];
            float2 xb = sx[t][blb];
            u64 qx = pk2(xa.x, xb.x);
            u64 qy = pk2(xa.y, xb.y);
            u64 s = gt1_2(m);
            m = fma2(m, BETA2, fma2(qx, w0p, mul2(qy, w1q)));
            m = fma2(s, NEG12, m);
            cnt = add2(cnt, gt1_2(m));              // spk_t, t in [118,127]
        }

        float ca, cb;
        unpk2(cnt, ca, cb);
        if (acta && ca != 0.f) {
            atomicAdd(&sAcc[bla][0], ca * sw20[ha]);
            atomicAdd(&sAcc[bla][1], ca * sw21[ha]);
        }
        if (actb && cb != 0.f) {
            atomicAdd(&sAcc[blb][0], cb * sw20[hb]);
            atomicAdd(&sAcc[blb][1], cb * sw21[hb]);
        }
    }
    __syncthreads();

    // ---- output: exclusive plain stores ----
    if (tid < TILE_B * 2) {
        int bl = tid >> 1, o = tid & 1;
        out[(b0 + bl) * 2 + o] = 0.1f * sAcc[bl][o];
    }
}

extern "C" void kernel_launch(void* const* d_in, const int* in_sizes, int n_in,
                              void* d_out, int out_size) {
    const float2* x  = (const float2*)d_in[0];   // [128, 8192, 2] f32
    const float2* W1 = (const float2*)d_in[1];   // [256, 2] f32
    const float*  W2 = (const float*)d_in[2];    // [2, 256] f32
    float* out = (float*)d_out;                  // [8192, 2] f32

    k_pre   <<<1, H_DIM>>>(W1, W2);
    snn_mega<<<B_TOT / TILE_B, 256>>>(x, out);
}